// round 14
// baseline (speedup 1.0000x reference)
#include <cuda_runtime.h>
#include <cuda_bf16.h>
#include <math.h>
#include <stdint.h>

// ===========================================================================
// CBTree B=4, L=9, d=256.
// h_par = tanh(G @ B^T + v),  G=[gl|gr] (M x 512),  B=[Wl|Wr] (256 x 512).
//   gl = c0 + (2/3)c1 + (1/3)c2 ;  gr = (1/3)c1 + (2/3)c2 + c3
// KEY CHANGE (R13): G is produced bf16 hi/lo by the PRODUCER (prep_G for
// leaves; level epilogues / reduce_G for interior), so the consumer mainloop
// has zero A-side register pressure -> 64 regs -> 2 CTAs/SM.
// l7: fused mma (z=1) -> G out.  l6: mma z=2 + reduce_G.  l5: mma z=4 +
// reduce_tanh -> h fp32.  l4..l0: fp32 SIMT small kernels on h.
// ===========================================================================

#define MTILE 64

#define ST_A_HI 0
#define ST_A_LO 4096
#define ST_B_HI 8192
#define ST_B_LO 24576
#define STAGE   40960
#define SMEM_REQ (2 * STAGE)  // 80 KB

#define SW(r, cb) ((uint32_t)((r) * 64 + (((cb) ^ (((r) >> 1) & 3)) << 4)))

// Scratch (__device__ globals: allocation-free rule)
__device__ __nv_bfloat16 g_LGhi[16384 * 512];  // leaf G hi (16 MB)
__device__ __nv_bfloat16 g_LGlo[16384 * 512];  // leaf G lo
__device__ __nv_bfloat16 g_G7hi[4096 * 512];   // G from l7 out
__device__ __nv_bfloat16 g_G7lo[4096 * 512];
__device__ __nv_bfloat16 g_G6hi[1024 * 512];   // G from l6 out
__device__ __nv_bfloat16 g_G6lo[1024 * 512];
__device__ float g_part[2097152];              // 8 MB K-split partials
__device__ float g_hs0[1024 * 256];            // h scratch ping
__device__ float g_hs1[256 * 256];             // h scratch pong
__device__ uint4 g_Bhi[256 * 512 / 8];         // bf16 [256][512] hi of [Wl|Wr]
__device__ uint4 g_Blo[256 * 512 / 8];

// ---------------------------------------------------------------------------
__device__ __forceinline__ uint32_t smem_u32(const void* p) {
    uint32_t a;
    asm("{ .reg .u64 t; cvta.to.shared.u64 t, %1; cvt.u32.u64 %0, t; }"
        : "=r"(a) : "l"(p));
    return a;
}
__device__ __forceinline__ void ldsm_x4(uint32_t* r, uint32_t addr) {
    asm volatile("ldmatrix.sync.aligned.m8n8.x4.shared.b16 {%0,%1,%2,%3}, [%4];"
                 : "=r"(r[0]), "=r"(r[1]), "=r"(r[2]), "=r"(r[3]) : "r"(addr));
}
__device__ __forceinline__ void mma16816(float* d, const uint32_t* a,
                                         const uint32_t* b) {
    asm volatile(
        "mma.sync.aligned.m16n8k16.row.col.f32.bf16.bf16.f32 "
        "{%0,%1,%2,%3}, {%4,%5,%6,%7}, {%8,%9}, {%0,%1,%2,%3};"
        : "+f"(d[0]), "+f"(d[1]), "+f"(d[2]), "+f"(d[3])
        : "r"(a[0]), "r"(a[1]), "r"(a[2]), "r"(a[3]), "r"(b[0]), "r"(b[1]));
}
__device__ __forceinline__ void cp_async16(uint32_t dst, const void* src) {
    asm volatile("cp.async.cg.shared.global [%0], [%1], 16;"
                 :: "r"(dst), "l"(src) : "memory");
}
#define CP_COMMIT() asm volatile("cp.async.commit_group;" ::: "memory")
#define CP_WAIT0()  asm volatile("cp.async.wait_group 0;" ::: "memory")

__device__ __forceinline__ void split2(float x, float y, uint32_t& hi, uint32_t& lo) {
    __nv_bfloat16 hx = __float2bfloat16(x);
    __nv_bfloat16 hy = __float2bfloat16(y);
    float rx = x - __bfloat162float(hx);
    float ry = y - __bfloat162float(hy);
    hi = (uint32_t)__bfloat16_as_ushort(hx) |
         ((uint32_t)__bfloat16_as_ushort(hy) << 16);
    lo = (uint32_t)__bfloat16_as_ushort(__float2bfloat16(rx)) |
         ((uint32_t)__bfloat16_as_ushort(__float2bfloat16(ry)) << 16);
}

// ---------------------------------------------------------------------------
// prep_G: leaf children -> leaf G bf16 hi/lo. One CTA per G row (q).
// ---------------------------------------------------------------------------
__global__ void __launch_bounds__(256) prep_G(const float* __restrict__ leaf) {
    const int q = blockIdx.x;
    const int j = threadIdx.x;
    const float* cb = leaf + (size_t)q * 1024;
    float c0 = cb[j], c1 = cb[256 + j], c2 = cb[512 + j], c3 = cb[768 + j];
    const float c23 = 2.0f / 3.0f, c13 = 1.0f / 3.0f;
    float gl = c0 + c23 * c1 + c13 * c2;
    float gr = c13 * c1 + c23 * c2 + c3;
    size_t o = (size_t)q * 512 + j;
    __nv_bfloat16 hl = __float2bfloat16(gl);
    __nv_bfloat16 hr = __float2bfloat16(gr);
    g_LGhi[o] = hl;
    g_LGhi[o + 256] = hr;
    g_LGlo[o] = __float2bfloat16(gl - __bfloat162float(hl));
    g_LGlo[o + 256] = __float2bfloat16(gr - __bfloat162float(hr));
}

// ---------------------------------------------------------------------------
__global__ void prep_b(const float* __restrict__ Wl, const float* __restrict__ Wr,
                       int base) {
    int idx = (base + blockIdx.x) * 256 + threadIdx.x;
    int n = idx >> 9, k = idx & 511;
    float w = (k < 256) ? Wl[n * 256 + k] : Wr[n * 256 + (k - 256)];
    __nv_bfloat16 h = __float2bfloat16(w);
    float r = w - __bfloat162float(h);
    ((unsigned short*)g_Bhi)[idx] = __bfloat16_as_ushort(h);
    ((unsigned short*)g_Blo)[idx] = __bfloat16_as_ushort(__float2bfloat16(r));
}

// ---------------------------------------------------------------------------
// HMMA level kernel. A = G bf16 hi/lo (pure cp.async). grid (n_par/64,1,z).
// z==1: +v, tanh, then produce G (GoutHi/GoutLo) via smem h-tile.
// z>1 : fp32 partial to part + z*zstride.
// ---------------------------------------------------------------------------
__global__ void __launch_bounds__(512, 2) level_mma(
    const __nv_bfloat16* __restrict__ Ghi,
    const __nv_bfloat16* __restrict__ Glo,
    const float* __restrict__ vecs,
    __nv_bfloat16* __restrict__ GoutHi,
    __nv_bfloat16* __restrict__ GoutLo,
    float* __restrict__ part,
    int nc, size_t zstride)
{
    extern __shared__ char smem[];
    const uint32_t sbase = smem_u32(smem);
    const int tid  = threadIdx.x;
    const int warp = tid >> 5;
    const int lane = tid & 31;
    const int wm   = warp & 1;          // M 32-block (0..1)
    const int wn   = warp >> 1;         // N 32-block (0..7)
    const int p0   = blockIdx.x * MTILE;
    const int c0   = blockIdx.z * nc;

    // ---- A fill: 512 slots = 64 rows x 4 cb x {hi,lo}; 1 cp.async/thread ----
    const int  aRow = (tid & 255) >> 2;
    const int  aCb  = tid & 3;
    const bool aHi  = (tid < 256);
    const uint32_t aDst = sbase + (aHi ? ST_A_HI : ST_A_LO) + SW(aRow, aCb);
    const __nv_bfloat16* aSrc =
        (aHi ? Ghi : Glo) + ((size_t)(p0 + aRow) * 512 + aCb * 8);

    // ---- B fill: rows fr and 128+fr ----
    const int fr  = tid >> 2, fcb = tid & 3;
    const uint32_t bswA = SW(fr, fcb);
    const uint32_t bswB = SW(128 + fr, fcb);
    const int giA = fr * 64 + fcb;
    const int giB = (128 + fr) * 64 + fcb;

    // ---- hoisted ldsm addressing ----
    uint32_t aAddr[2][2], bAddr[2][2];
#pragma unroll
    for (int ks = 0; ks < 2; ks++) {
        const int acb = ks * 2 + (lane >> 4);
        const int arow = wm * 32 + (lane & 15);
#pragma unroll
        for (int mi = 0; mi < 2; mi++)
            aAddr[ks][mi] = sbase + ST_A_HI + SW(arow + mi * 16, acb);
#pragma unroll
        for (int nq = 0; nq < 2; nq++) {
            const int brow = wn * 32 + nq * 16 + (lane & 15);
            bAddr[ks][nq] = sbase + ST_B_HI + SW(brow, acb);
        }
    }

    float acc[2][4][4];
#pragma unroll
    for (int i = 0; i < 2; i++)
#pragma unroll
        for (int j = 0; j < 4; j++)
#pragma unroll
            for (int q = 0; q < 4; q++) acc[i][j][q] = 0.0f;

    auto fill = [&](int c, uint32_t stOff) {
        cp_async16(aDst + stOff, aSrc + c * 32);
        const uint32_t st = sbase + stOff;
        const int cc = c * 4;
        cp_async16(st + ST_B_HI + bswA, g_Bhi + giA + cc);
        cp_async16(st + ST_B_LO + bswA, g_Blo + giA + cc);
        cp_async16(st + ST_B_HI + bswB, g_Bhi + giB + cc);
        cp_async16(st + ST_B_LO + bswB, g_Blo + giB + cc);
    };

    fill(c0, 0);
    CP_COMMIT();

    for (int i = 0; i < nc; i++) {
        const int c = c0 + i;
        const uint32_t sOff = (i & 1) ? STAGE : 0;
        const uint32_t sOffN = sOff ^ STAGE;
        CP_WAIT0();
        __syncthreads();   // stage ready + prev readers drained

        const bool more = (i + 1 < nc);
        if (more) {
            fill(c + 1, sOffN);
            CP_COMMIT();
        }

#pragma unroll
        for (int ks = 0; ks < 2; ks++) {
            uint32_t ah[2][4], al[2][4];
#pragma unroll
            for (int mi = 0; mi < 2; mi++) {
                const uint32_t ad = aAddr[ks][mi] + sOff;
                ldsm_x4(ah[mi], ad);
                ldsm_x4(al[mi], ad + (ST_A_LO - ST_A_HI));
            }
#pragma unroll
            for (int nq = 0; nq < 2; nq++) {
                const uint32_t bd = bAddr[ks][nq] + sOff;
                uint32_t qh[4], ql[4];
                ldsm_x4(qh, bd);
                ldsm_x4(ql, bd + (ST_B_LO - ST_B_HI));
                uint32_t bh0[2] = {qh[0], qh[2]}, bh1[2] = {qh[1], qh[3]};
                uint32_t bl0[2] = {ql[0], ql[2]}, bl1[2] = {ql[1], ql[3]};
#pragma unroll
                for (int mi = 0; mi < 2; mi++) {
                    mma16816(acc[mi][nq * 2],     ah[mi], bh0);
                    mma16816(acc[mi][nq * 2],     al[mi], bh0);
                    mma16816(acc[mi][nq * 2],     ah[mi], bl0);
                    mma16816(acc[mi][nq * 2 + 1], ah[mi], bh1);
                    mma16816(acc[mi][nq * 2 + 1], al[mi], bh1);
                    mma16816(acc[mi][nq * 2 + 1], ah[mi], bl1);
                }
            }
        }
    }

    if (gridDim.z == 1) {
        // ---- fused: +v, tanh -> smem h tile -> combine -> G out ----
        __syncthreads();                         // mainloop smem reads done
        float* sh = (float*)smem;                // [64][260]
#pragma unroll
        for (int mi = 0; mi < 2; mi++) {
            const int lr0 = wm * 32 + mi * 16 + (lane >> 2);
            const int lr1 = lr0 + 8;
#pragma unroll
            for (int nj = 0; nj < 4; nj++) {
                const int col = wn * 32 + nj * 8 + (lane & 3) * 2;
                float2 v0 = *(const float2*)(vecs + (size_t)(p0 + lr0) * 256 + col);
                float2 v1 = *(const float2*)(vecs + (size_t)(p0 + lr1) * 256 + col);
                sh[lr0 * 260 + col]     = tanhf(acc[mi][nj][0] + v0.x);
                sh[lr0 * 260 + col + 1] = tanhf(acc[mi][nj][1] + v0.y);
                sh[lr1 * 260 + col]     = tanhf(acc[mi][nj][2] + v1.x);
                sh[lr1 * 260 + col + 1] = tanhf(acc[mi][nj][3] + v1.y);
            }
        }
        __syncthreads();
        // combine 4 rows -> G (16 G rows x 512); thread -> (q, side, 16 cols)
        const int q    = tid >> 5;
        const int side = (tid >> 4) & 1;
        const int j0   = (tid & 15) * 16;
        const float w0 = side ? (1.0f / 3.0f) : 1.0f;
        const float w1 = 2.0f / 3.0f;
        const float w2 = side ? 1.0f : (1.0f / 3.0f);
        const float* r0 = sh + (4 * q + side) * 260 + j0;
        uint32_t hp[8], lp[8];
#pragma unroll
        for (int k = 0; k < 8; k++) {
            float ga = w0 * r0[2 * k]     + w1 * r0[260 + 2 * k]     + w2 * r0[520 + 2 * k];
            float gb = w0 * r0[2 * k + 1] + w1 * r0[260 + 2 * k + 1] + w2 * r0[520 + 2 * k + 1];
            split2(ga, gb, hp[k], lp[k]);
        }
        const size_t go = (size_t)(p0 / 4 + q) * 512 + side * 256 + j0;
        ((uint4*)(GoutHi + go))[0] = make_uint4(hp[0], hp[1], hp[2], hp[3]);
        ((uint4*)(GoutHi + go))[1] = make_uint4(hp[4], hp[5], hp[6], hp[7]);
        ((uint4*)(GoutLo + go))[0] = make_uint4(lp[0], lp[1], lp[2], lp[3]);
        ((uint4*)(GoutLo + go))[1] = make_uint4(lp[4], lp[5], lp[6], lp[7]);
    } else {
        float* dst = part + (size_t)blockIdx.z * zstride;
#pragma unroll
        for (int mi = 0; mi < 2; mi++) {
            const int r0 = p0 + wm * 32 + mi * 16 + (lane >> 2);
            const int r1 = r0 + 8;
#pragma unroll
            for (int nj = 0; nj < 4; nj++) {
                const int col = wn * 32 + nj * 8 + (lane & 3) * 2;
                *(float2*)(dst + (size_t)r0 * 256 + col) =
                    make_float2(acc[mi][nj][0], acc[mi][nj][1]);
                *(float2*)(dst + (size_t)r1 * 256 + col) =
                    make_float2(acc[mi][nj][2], acc[mi][nj][3]);
            }
        }
    }
}

// ---------------------------------------------------------------------------
// reduce_G: sum K-split partials, +v, tanh -> smem h tile -> G bf16 hi/lo.
// grid = n_par/64, 256 thr, dynamic smem 64*260*4.
// ---------------------------------------------------------------------------
__global__ void __launch_bounds__(256) reduce_G(
    const float* __restrict__ part, const float* __restrict__ vecs,
    __nv_bfloat16* __restrict__ GoutHi, __nv_bfloat16* __restrict__ GoutLo,
    int nsplit, size_t zstride)
{
    extern __shared__ float sh[];                // [64][260]
    const int tid = threadIdx.x;
    const int R = blockIdx.x * 64;
#pragma unroll 4
    for (int k = 0; k < 16; k++) {
        int fidx = k * 256 + tid;                // 4096 float4s
        int row = fidx >> 6, c4 = (fidx & 63) * 4;
        size_t o = (size_t)(R + row) * 256 + c4;
        float4 s = *(const float4*)(part + o);
        for (int z = 1; z < nsplit; z++) {
            float4 t = *(const float4*)(part + (size_t)z * zstride + o);
            s.x += t.x; s.y += t.y; s.z += t.z; s.w += t.w;
        }
        float4 v = *(const float4*)(vecs + o);
        float4 r;
        r.x = tanhf(s.x + v.x);
        r.y = tanhf(s.y + v.y);
        r.z = tanhf(s.z + v.z);
        r.w = tanhf(s.w + v.w);
        *(float4*)(sh + row * 260 + c4) = r;
    }
    __syncthreads();
    // 16 G rows x 512 cols / 256 thr: (q, side via 2 iter, 16 cols)
    const int q  = tid >> 4;
    const int j0 = (tid & 15) * 16;
#pragma unroll
    for (int side = 0; side < 2; side++) {
        const float w0 = side ? (1.0f / 3.0f) : 1.0f;
        const float w1 = 2.0f / 3.0f;
        const float w2 = side ? 1.0f : (1.0f / 3.0f);
        const float* r0 = sh + (4 * q + side) * 260 + j0;
        uint32_t hp[8], lp[8];
#pragma unroll
        for (int k = 0; k < 8; k++) {
            float ga = w0 * r0[2 * k]     + w1 * r0[260 + 2 * k]     + w2 * r0[520 + 2 * k];
            float gb = w0 * r0[2 * k + 1] + w1 * r0[260 + 2 * k + 1] + w2 * r0[520 + 2 * k + 1];
            split2(ga, gb, hp[k], lp[k]);
        }
        const size_t go = (size_t)(R / 4 + q) * 512 + side * 256 + j0;
        ((uint4*)(GoutHi + go))[0] = make_uint4(hp[0], hp[1], hp[2], hp[3]);
        ((uint4*)(GoutHi + go))[1] = make_uint4(hp[4], hp[5], hp[6], hp[7]);
        ((uint4*)(GoutLo + go))[0] = make_uint4(lp[0], lp[1], lp[2], lp[3]);
        ((uint4*)(GoutLo + go))[1] = make_uint4(lp[4], lp[5], lp[6], lp[7]);
    }
}

// ---------------------------------------------------------------------------
__global__ void __launch_bounds__(256) reduce_tanh(
    const float* __restrict__ part, const float* __restrict__ vecs,
    float* __restrict__ out, int nsplit, size_t zstride)
{
    size_t i = (size_t)blockIdx.x * 256 + threadIdx.x;   // float4 index
    float4 s = ((const float4*)part)[i];
    for (int z = 1; z < nsplit; z++) {
        float4 t = *(const float4*)(part + z * zstride + i * 4);
        s.x += t.x; s.y += t.y; s.z += t.z; s.w += t.w;
    }
    float4 v = ((const float4*)vecs)[i];
    float4 r;
    r.x = tanhf(s.x + v.x);
    r.y = tanhf(s.y + v.y);
    r.z = tanhf(s.z + v.z);
    r.w = tanhf(s.w + v.w);
    ((float4*)out)[i] = r;
}

// ---------------------------------------------------------------------------
__global__ void __launch_bounds__(256) level_small(
    const float* __restrict__ childs,
    const float* __restrict__ Wl,
    const float* __restrict__ Wr,
    const float* __restrict__ vecs,
    float* __restrict__ out)
{
    __shared__ float G[512];
    __shared__ float partl[8][33];
    const int tid = threadIdx.x;
    const int p   = blockIdx.x >> 3;
    const int cg  = blockIdx.x & 7;
    const float c23 = 2.0f / 3.0f, c13 = 1.0f / 3.0f;

    {
        const float* cb = childs + (size_t)p * 1024;
        int j = tid;
        G[j] = cb[j] + c23 * cb[256 + j] + c13 * cb[512 + j];
        G[256 + j] = c13 * cb[256 + j] + c23 * cb[512 + j] + cb[768 + j];
    }
    __syncthreads();

    const int cc = tid & 31;
    const int kg = tid >> 5;
    const int n  = cg * 32 + cc;
    const float* src = (kg < 4) ? (Wl + (size_t)n * 256 + kg * 64)
                                : (Wr + (size_t)n * 256 + (kg - 4) * 64);
    const float* g = G + kg * 64;

    float a0 = 0.f, a1 = 0.f, a2 = 0.f, a3 = 0.f;
#pragma unroll
    for (int i = 0; i < 64; i += 4) {
        float4 w = *(const float4*)(src + i);
        float4 gg = *(const float4*)(g + i);
        a0 = fmaf(gg.x, w.x, a0);
        a1 = fmaf(gg.y, w.y, a1);
        a2 = fmaf(gg.z, w.z, a2);
        a3 = fmaf(gg.w, w.w, a3);
    }
    partl[kg][cc] = (a0 + a1) + (a2 + a3);
    __syncthreads();

    if (tid < 32) {
        float s = 0.f;
#pragma unroll
        for (int k = 0; k < 8; k++) s += partl[k][tid];
        const int col = cg * 32 + tid;
        out[(size_t)p * 256 + col] = tanhf(s + vecs[(size_t)p * 256 + col]);
    }
}

// ---------------------------------------------------------------------------
extern "C" void kernel_launch(void* const* d_in, const int* in_sizes, int n_in,
                              void* d_out, int out_size) {
    const float* vectors = (const float*)d_in[0];
    const float* Wl = (const float*)d_in[1];
    const float* Wr = (const float*)d_in[2];

    static __nv_bfloat16 *LGhi, *LGlo, *G7hi, *G7lo, *G6hi, *G6lo;
    static float *part, *hs0, *hs1;
    static bool inited = false;
    if (!inited) {
        cudaGetSymbolAddress((void**)&LGhi, g_LGhi);
        cudaGetSymbolAddress((void**)&LGlo, g_LGlo);
        cudaGetSymbolAddress((void**)&G7hi, g_G7hi);
        cudaGetSymbolAddress((void**)&G7lo, g_G7lo);
        cudaGetSymbolAddress((void**)&G6hi, g_G6hi);
        cudaGetSymbolAddress((void**)&G6lo, g_G6lo);
        cudaGetSymbolAddress((void**)&part, g_part);
        cudaGetSymbolAddress((void**)&hs0, g_hs0);
        cudaGetSymbolAddress((void**)&hs1, g_hs1);
        cudaFuncSetAttribute(level_mma,
                             cudaFuncAttributeMaxDynamicSharedMemorySize, SMEM_REQ);
        cudaFuncSetAttribute(level_mma,
                             cudaFuncAttributePreferredSharedMemoryCarveout, 100);
        cudaFuncSetAttribute(reduce_G,
                             cudaFuncAttributeMaxDynamicSharedMemorySize, 64 * 260 * 4);
        inited = true;
    }

    const float* leaves = vectors + (size_t)21845 * 256;
    const float* v7 = vectors + (size_t)5461 * 256;
    const float* v6 = vectors + (size_t)1365 * 256;
    const float* v5 = vectors + (size_t)341 * 256;
    const float* v4 = vectors + (size_t)85 * 256;
    const float* v3 = vectors + (size_t)21 * 256;
    const float* v2 = vectors + (size_t)5 * 256;
    const float* v1 = vectors + (size_t)1 * 256;
    const float* v0 = vectors;

    // slots 0-2: prep; slot 3 = l7 level_mma (ncu capture)
    prep_G<<<16384, 256>>>(leaves);
    prep_b<<<256, 256>>>(Wl, Wr, 0);
    prep_b<<<256, 256>>>(Wl, Wr, 256);

    // l7: 16384 parents, fused, produces G7
    level_mma<<<dim3(256, 1, 1), 512, SMEM_REQ>>>(
        LGhi, LGlo, v7, G7hi, G7lo, part, 16, 0);
    // l6: 4096 parents, z=2 -> reduce_G -> G6
    level_mma<<<dim3(64, 1, 2), 512, SMEM_REQ>>>(
        G7hi, G7lo, nullptr, nullptr, nullptr, part, 8, 1048576);
    reduce_G<<<64, 256, 64 * 260 * 4>>>(part, v6, G6hi, G6lo, 2, 1048576);
    // l5: 1024 parents, z=4 -> reduce_tanh -> h fp32
    level_mma<<<dim3(16, 1, 4), 512, SMEM_REQ>>>(
        G6hi, G6lo, nullptr, nullptr, nullptr, part, 4, 262144);
    reduce_tanh<<<256, 256>>>(part, v5, hs0, 4, 262144);
    // l4..l0: fp32 SIMT chain on h
    level_small<<<256 * 8, 256>>>(hs0, Wl, Wr, v4, hs1);
    level_small<<<64 * 8, 256>>>(hs1, Wl, Wr, v3, hs0);
    level_small<<<16 * 8, 256>>>(hs0, Wl, Wr, v2, hs1);
    level_small<<<4 * 8, 256>>>(hs1, Wl, Wr, v1, hs0);
    level_small<<<1 * 8, 256>>>(hs0, Wl, Wr, v0, (float*)d_out);
}

// round 15
// speedup vs baseline: 1.1807x; 1.1807x over previous
#include <cuda_runtime.h>
#include <cuda_bf16.h>
#include <math.h>
#include <stdint.h>

// ===========================================================================
// CBTree B=4, L=9, d=256.
// h_par = tanh(G @ B^T + v),  G=[gl|gr] (M x 512),  B=[Wl|Wr] (256 x 512).
//   gl = c0 + (2/3)c1 + (1/3)c2 ;  gr = (1/3)c1 + (2/3)c2 + c3
// R15 = best-of-all-rounds composition:
//   l7: WIDE mma (512thr, 64x256, in-loop A, fused v+tanh) - R12, 64.9us
//   l6: NARROW mma (256thr, 64x128, 2 CTA/SM) z=4 + reduce  - R8 shape
//   l5: NARROW mma z=8 + reduce
//   l4..l0: fp32 SIMT smalls
// 3-pass bf16 hi/lo HMMA numerics (validated, rel_err ~7e-6) throughout.
// ===========================================================================

#define MTILE 64

// ---- narrow kernel smem layout (24KB/stage) ----
#define N_A_HI 0
#define N_A_LO 4096
#define N_B_HI 8192
#define N_B_LO 16384
#define N_STAGE 24576
#define N_SMEM (2 * N_STAGE)   // 48 KB

// ---- wide kernel smem layout (40KB/stage) ----
#define W_A_HI 0
#define W_A_LO 4096
#define W_B_HI 8192
#define W_B_LO 24576
#define W_STAGE 40960
#define W_SMEM (2 * W_STAGE)   // 80 KB

#define SW(r, cb) ((uint32_t)((r) * 64 + (((cb) ^ (((r) >> 1) & 3)) << 4)))

__device__ float g_h0[16384 * 256];      // 16 MB h ping
__device__ float g_h1[16384 * 256];      // 16 MB h pong
__device__ float g_part[4194304];        // 16 MB K-split partials
__device__ uint4 g_Bhi[256 * 512 / 8];   // bf16 [256][512] hi of [Wl|Wr]
__device__ uint4 g_Blo[256 * 512 / 8];   // bf16 [256][512] lo

// ---------------------------------------------------------------------------
__device__ __forceinline__ uint32_t smem_u32(const void* p) {
    uint32_t a;
    asm("{ .reg .u64 t; cvta.to.shared.u64 t, %1; cvt.u32.u64 %0, t; }"
        : "=r"(a) : "l"(p));
    return a;
}
__device__ __forceinline__ void ldsm_x4(uint32_t* r, uint32_t addr) {
    asm volatile("ldmatrix.sync.aligned.m8n8.x4.shared.b16 {%0,%1,%2,%3}, [%4];"
                 : "=r"(r[0]), "=r"(r[1]), "=r"(r[2]), "=r"(r[3]) : "r"(addr));
}
__device__ __forceinline__ void mma16816(float* d, const uint32_t* a,
                                         const uint32_t* b) {
    asm volatile(
        "mma.sync.aligned.m16n8k16.row.col.f32.bf16.bf16.f32 "
        "{%0,%1,%2,%3}, {%4,%5,%6,%7}, {%8,%9}, {%0,%1,%2,%3};"
        : "+f"(d[0]), "+f"(d[1]), "+f"(d[2]), "+f"(d[3])
        : "r"(a[0]), "r"(a[1]), "r"(a[2]), "r"(a[3]), "r"(b[0]), "r"(b[1]));
}
__device__ __forceinline__ void cp_async16(uint32_t dst, const void* src) {
    asm volatile("cp.async.cg.shared.global [%0], [%1], 16;"
                 :: "r"(dst), "l"(src) : "memory");
}
#define CP_COMMIT() asm volatile("cp.async.commit_group;" ::: "memory")
#define CP_WAIT0()  asm volatile("cp.async.wait_group 0;" ::: "memory")

__device__ __forceinline__ void split2(float x, float y, uint32_t& hi, uint32_t& lo) {
    __nv_bfloat16 hx = __float2bfloat16(x);
    __nv_bfloat16 hy = __float2bfloat16(y);
    float rx = x - __bfloat162float(hx);
    float ry = y - __bfloat162float(hy);
    hi = (uint32_t)__bfloat16_as_ushort(hx) |
         ((uint32_t)__bfloat16_as_ushort(hy) << 16);
    lo = (uint32_t)__bfloat16_as_ushort(__float2bfloat16(rx)) |
         ((uint32_t)__bfloat16_as_ushort(__float2bfloat16(ry)) << 16);
}

// ---------------------------------------------------------------------------
__global__ void prep_b(const float* __restrict__ Wl, const float* __restrict__ Wr) {
    int idx = blockIdx.x * 256 + threadIdx.x;   // grid 512
    int n = idx >> 9, k = idx & 511;
    float w = (k < 256) ? Wl[n * 256 + k] : Wr[n * 256 + (k - 256)];
    __nv_bfloat16 h = __float2bfloat16(w);
    float r = w - __bfloat162float(h);
    ((unsigned short*)g_Bhi)[idx] = __bfloat16_as_ushort(h);
    ((unsigned short*)g_Blo)[idx] = __bfloat16_as_ushort(__float2bfloat16(r));
}

// ===========================================================================
// WIDE kernel (l7): 512 thr, CTA 64(M) x 256(N), in-loop A, fused epilogue.
// ===========================================================================
__global__ void __launch_bounds__(512) mma_l7(
    const float* __restrict__ childs,
    const float* __restrict__ vecs,
    float* __restrict__ out)
{
    extern __shared__ char smem[];
    const uint32_t sbase = smem_u32(smem);
    const int tid  = threadIdx.x;
    const int warp = tid >> 5;
    const int lane = tid & 31;
    const int wm   = warp & 1;
    const int wn   = warp >> 1;
    const int p0   = blockIdx.x * MTILE;

    // B fill: rows fr and 128+fr
    const int fr  = tid >> 2, fcb = tid & 3;
    const uint32_t bswA = SW(fr, fcb);
    const uint32_t bswB = SW(128 + fr, fcb);
    const int giA = fr * 64 + fcb;
    const int giB = (128 + fr) * 64 + fcb;
    const bool aThread = (tid < 256);
    const uint32_t asw = bswA;                       // A row fr (0..63)
    const float* cbbase = childs + (size_t)(p0 + fr) * 1024 + fcb * 8;

    uint32_t aAddr[2][2], bAddr[2][2];
#pragma unroll
    for (int ks = 0; ks < 2; ks++) {
        const int acb = ks * 2 + (lane >> 4);
        const int arow = wm * 32 + (lane & 15);
#pragma unroll
        for (int mi = 0; mi < 2; mi++)
            aAddr[ks][mi] = sbase + W_A_HI + SW(arow + mi * 16, acb);
#pragma unroll
        for (int nq = 0; nq < 2; nq++) {
            const int brow = wn * 32 + nq * 16 + (lane & 15);
            bAddr[ks][nq] = sbase + W_B_HI + SW(brow, acb);
        }
    }

    float acc[2][4][4];
#pragma unroll
    for (int i = 0; i < 2; i++)
#pragma unroll
        for (int j = 0; j < 4; j++)
#pragma unroll
            for (int q = 0; q < 4; q++) acc[i][j][q] = 0.0f;

    float4 ra0, ra1, rb0, rb1, rd0, rd1;

    auto load_A = [&](int c) {
        if (!aThread) return;
        const bool left = (c < 8);
        const float* cb = cbbase + (left ? c * 32 : ((c - 8) * 32 + 256));
        ra0 = *(const float4*)(cb);
        ra1 = *(const float4*)(cb + 4);
        rb0 = *(const float4*)(cb + 256);
        rb1 = *(const float4*)(cb + 260);
        rd0 = *(const float4*)(cb + 512);
        rd1 = *(const float4*)(cb + 516);
    };
    auto store_A = [&](int c, uint32_t stOff) {
        if (!aThread) return;
        const bool left = (c < 8);
        const float w0 = left ? 1.0f : (1.0f / 3.0f);
        const float w1 = 2.0f / 3.0f;
        const float w2 = left ? (1.0f / 3.0f) : 1.0f;
        float g0 = w0 * ra0.x + w1 * rb0.x + w2 * rd0.x;
        float g1 = w0 * ra0.y + w1 * rb0.y + w2 * rd0.y;
        float g2 = w0 * ra0.z + w1 * rb0.z + w2 * rd0.z;
        float g3 = w0 * ra0.w + w1 * rb0.w + w2 * rd0.w;
        float g4 = w0 * ra1.x + w1 * rb1.x + w2 * rd1.x;
        float g5 = w0 * ra1.y + w1 * rb1.y + w2 * rd1.y;
        float g6 = w0 * ra1.z + w1 * rb1.z + w2 * rd1.z;
        float g7 = w0 * ra1.w + w1 * rb1.w + w2 * rd1.w;
        uint4 uh, ul;
        split2(g0, g1, uh.x, ul.x);
        split2(g2, g3, uh.y, ul.y);
        split2(g4, g5, uh.z, ul.z);
        split2(g6, g7, uh.w, ul.w);
        char* st = smem + stOff;
        *(uint4*)(st + W_A_HI + asw) = uh;
        *(uint4*)(st + W_A_LO + asw) = ul;
    };
    auto fill_B = [&](int c, uint32_t stOff) {
        const uint32_t st = sbase + stOff;
        const int cc = c * 4;
        cp_async16(st + W_B_HI + bswA, g_Bhi + giA + cc);
        cp_async16(st + W_B_LO + bswA, g_Blo + giA + cc);
        cp_async16(st + W_B_HI + bswB, g_Bhi + giB + cc);
        cp_async16(st + W_B_LO + bswB, g_Blo + giB + cc);
    };

    load_A(0);
    fill_B(0, 0);
    CP_COMMIT();
    store_A(0, 0);

    for (int i = 0; i < 16; i++) {
        const uint32_t sOff = (i & 1) ? W_STAGE : 0;
        const uint32_t sOffN = sOff ^ W_STAGE;
        CP_WAIT0();
        __syncthreads();

        const bool more = (i + 1 < 16);
        if (more) {
            load_A(i + 1);
            fill_B(i + 1, sOffN);
            CP_COMMIT();
        }

#pragma unroll
        for (int ks = 0; ks < 2; ks++) {
            uint32_t ah[2][4], al[2][4];
#pragma unroll
            for (int mi = 0; mi < 2; mi++) {
                const uint32_t ad = aAddr[ks][mi] + sOff;
                ldsm_x4(ah[mi], ad);
                ldsm_x4(al[mi], ad + (W_A_LO - W_A_HI));
            }
#pragma unroll
            for (int nq = 0; nq < 2; nq++) {
                const uint32_t bd = bAddr[ks][nq] + sOff;
                uint32_t qh[4], ql[4];
                ldsm_x4(qh, bd);
                ldsm_x4(ql, bd + (W_B_LO - W_B_HI));
                uint32_t bh0[2] = {qh[0], qh[2]}, bh1[2] = {qh[1], qh[3]};
                uint32_t bl0[2] = {ql[0], ql[2]}, bl1[2] = {ql[1], ql[3]};
#pragma unroll
                for (int mi = 0; mi < 2; mi++) {
                    mma16816(acc[mi][nq * 2],     ah[mi], bh0);
                    mma16816(acc[mi][nq * 2],     al[mi], bh0);
                    mma16816(acc[mi][nq * 2],     ah[mi], bl0);
                    mma16816(acc[mi][nq * 2 + 1], ah[mi], bh1);
                    mma16816(acc[mi][nq * 2 + 1], al[mi], bh1);
                    mma16816(acc[mi][nq * 2 + 1], ah[mi], bl1);
                }
            }
        }
        if (more) store_A(i + 1, sOffN);
    }

    // fused epilogue: +v, tanh -> out (fp32 h)
#pragma unroll
    for (int mi = 0; mi < 2; mi++) {
        const int r0 = p0 + wm * 32 + mi * 16 + (lane >> 2);
        const int r1 = r0 + 8;
#pragma unroll
        for (int nj = 0; nj < 4; nj++) {
            const int col = wn * 32 + nj * 8 + (lane & 3) * 2;
            float2 v0 = *(const float2*)(vecs + (size_t)r0 * 256 + col);
            float2 v1 = *(const float2*)(vecs + (size_t)r1 * 256 + col);
            float2 q0, q1;
            q0.x = tanhf(acc[mi][nj][0] + v0.x);
            q0.y = tanhf(acc[mi][nj][1] + v0.y);
            q1.x = tanhf(acc[mi][nj][2] + v1.x);
            q1.y = tanhf(acc[mi][nj][3] + v1.y);
            *(float2*)(out + (size_t)r0 * 256 + col) = q0;
            *(float2*)(out + (size_t)r1 * 256 + col) = q1;
        }
    }
}

// ===========================================================================
// NARROW kernel (l6/l5): 256 thr, CTA 64(M) x 128(N), in-loop A, K-split.
// Exact R8-proven shape. grid (n_par/64, 2, z); partial fp32 to part.
// ===========================================================================
struct ARegs { float4 a0, a1, b0, b1, d0, d1; };

__device__ __forceinline__ void n_load_A(int c, const float* __restrict__ childs,
                                         int p0, int tid, ARegs& ar) {
    const bool left = (c < 8);
    const int row = tid >> 2, cblk = tid & 3;
    const int j0 = (left ? c * 32 : (c - 8) * 32) + cblk * 8;
    const int o0 = left ? 0 : 256;
    const float* cb = childs + (size_t)(p0 + row) * 1024 + j0;
    ar.a0 = *(const float4*)(cb + o0);
    ar.a1 = *(const float4*)(cb + o0 + 4);
    ar.b0 = *(const float4*)(cb + o0 + 256);
    ar.b1 = *(const float4*)(cb + o0 + 260);
    ar.d0 = *(const float4*)(cb + o0 + 512);
    ar.d1 = *(const float4*)(cb + o0 + 516);
}

__device__ __forceinline__ void n_store_A(int c, const ARegs& ar, char* st, int tid) {
    const bool left = (c < 8);
    const float w0 = left ? 1.0f : (1.0f / 3.0f);
    const float w1 = 2.0f / 3.0f;
    const float w2 = left ? (1.0f / 3.0f) : 1.0f;
    float g0 = w0 * ar.a0.x + w1 * ar.b0.x + w2 * ar.d0.x;
    float g1 = w0 * ar.a0.y + w1 * ar.b0.y + w2 * ar.d0.y;
    float g2 = w0 * ar.a0.z + w1 * ar.b0.z + w2 * ar.d0.z;
    float g3 = w0 * ar.a0.w + w1 * ar.b0.w + w2 * ar.d0.w;
    float g4 = w0 * ar.a1.x + w1 * ar.b1.x + w2 * ar.d1.x;
    float g5 = w0 * ar.a1.y + w1 * ar.b1.y + w2 * ar.d1.y;
    float g6 = w0 * ar.a1.z + w1 * ar.b1.z + w2 * ar.d1.z;
    float g7 = w0 * ar.a1.w + w1 * ar.b1.w + w2 * ar.d1.w;
    uint4 uh, ul;
    split2(g0, g1, uh.x, ul.x);
    split2(g2, g3, uh.y, ul.y);
    split2(g4, g5, uh.z, ul.z);
    split2(g6, g7, uh.w, ul.w);
    const int row = tid >> 2, cblk = tid & 3;
    uint32_t sw = SW(row, cblk);
    *(uint4*)(st + N_A_HI + sw) = uh;
    *(uint4*)(st + N_A_LO + sw) = ul;
}

__device__ __forceinline__ void n_fill_B(uint32_t stage, int c, int n0, int tid) {
#pragma unroll
    for (int it = 0; it < 2; it++) {
        int idx  = it * 256 + tid;
        int row  = idx >> 2, cblk = idx & 3;
        int gi   = (n0 + row) * 64 + c * 4 + cblk;
        uint32_t sw = SW(row, cblk);
        cp_async16(stage + N_B_HI + sw, g_Bhi + gi);
        cp_async16(stage + N_B_LO + sw, g_Blo + gi);
    }
}

__global__ void __launch_bounds__(256, 2) mma_mid(
    const float* __restrict__ childs,
    float* __restrict__ part,
    int nc, size_t zstride)
{
    extern __shared__ char smem[];
    const uint32_t sbase = smem_u32(smem);
    const int tid  = threadIdx.x;
    const int warp = tid >> 5;
    const int lane = tid & 31;
    const int wm   = warp & 1;
    const int wn   = warp >> 1;
    const int p0   = blockIdx.x * MTILE;
    const int n0   = blockIdx.y * 128;
    const int c0   = blockIdx.z * nc;

    float acc[2][4][4];
#pragma unroll
    for (int i = 0; i < 2; i++)
#pragma unroll
        for (int j = 0; j < 4; j++)
#pragma unroll
            for (int q = 0; q < 4; q++) acc[i][j][q] = 0.0f;

    ARegs ar;
    n_load_A(c0, childs, p0, tid, ar);
    n_fill_B(sbase, c0, n0, tid);
    CP_COMMIT();
    n_store_A(c0, ar, smem, tid);

    for (int i = 0; i < nc; i++) {
        const int c = c0 + i;
        const int s = i & 1;
        CP_WAIT0();
        __syncthreads();

        const bool more = (i + 1 < nc);
        if (more) {
            n_load_A(c + 1, childs, p0, tid, ar);
            n_fill_B(sbase + (s ^ 1) * N_STAGE, c + 1, n0, tid);
            CP_COMMIT();
        }

        const uint32_t sA = sbase + s * N_STAGE;
#pragma unroll
        for (int ks = 0; ks < 2; ks++) {
            const int acb = ks * 2 + (lane >> 4);
            uint32_t ah[2][4], al[2][4];
            const int arow = wm * 32 + (lane & 15);
#pragma unroll
            for (int mi = 0; mi < 2; mi++) {
                uint32_t ad = sA + N_A_HI + SW(arow + mi * 16, acb);
                ldsm_x4(ah[mi], ad);
                ldsm_x4(al[mi], ad + (N_A_LO - N_A_HI));
            }
#pragma unroll
            for (int nq = 0; nq < 2; nq++) {
                const int brow = wn * 32 + nq * 16 + (lane & 15);
                uint32_t bd = sA + N_B_HI + SW(brow, acb);
                uint32_t qh[4], ql[4];
                ldsm_x4(qh, bd);
                ldsm_x4(ql, bd + (N_B_LO - N_B_HI));
                uint32_t bh0[2] = {qh[0], qh[2]}, bh1[2] = {qh[1], qh[3]};
                uint32_t bl0[2] = {ql[0], ql[2]}, bl1[2] = {ql[1], ql[3]};
#pragma unroll
                for (int mi = 0; mi < 2; mi++) {
                    mma16816(acc[mi][nq * 2],     ah[mi], bh0);
                    mma16816(acc[mi][nq * 2],     al[mi], bh0);
                    mma16816(acc[mi][nq * 2],     ah[mi], bl0);
                    mma16816(acc[mi][nq * 2 + 1], ah[mi], bh1);
                    mma16816(acc[mi][nq * 2 + 1], al[mi], bh1);
                    mma16816(acc[mi][nq * 2 + 1], ah[mi], bl1);
                }
            }
        }
        if (more) n_store_A(c + 1, ar, smem + (s ^ 1) * N_STAGE, tid);
        __syncthreads();
    }

    float* dst = part + (size_t)blockIdx.z * zstride;
#pragma unroll
    for (int mi = 0; mi < 2; mi++) {
        const int r0 = p0 + wm * 32 + mi * 16 + (lane >> 2);
        const int r1 = r0 + 8;
#pragma unroll
        for (int nj = 0; nj < 4; nj++) {
            const int col = n0 + wn * 32 + nj * 8 + (lane & 3) * 2;
            *(float2*)(dst + (size_t)r0 * 256 + col) =
                make_float2(acc[mi][nj][0], acc[mi][nj][1]);
            *(float2*)(dst + (size_t)r1 * 256 + col) =
                make_float2(acc[mi][nj][2], acc[mi][nj][3]);
        }
    }
}

// ---------------------------------------------------------------------------
__global__ void __launch_bounds__(256) reduce_tanh(
    const float* __restrict__ part, const float* __restrict__ vecs,
    float* __restrict__ out, int nsplit, size_t zstride)
{
    size_t i = (size_t)blockIdx.x * 256 + threadIdx.x;   // float4 index
    float4 s = ((const float4*)part)[i];
    for (int z = 1; z < nsplit; z++) {
        float4 t = *(const float4*)(part + z * zstride + i * 4);
        s.x += t.x; s.y += t.y; s.z += t.z; s.w += t.w;
    }
    float4 v = ((const float4*)vecs)[i];
    float4 r;
    r.x = tanhf(s.x + v.x);
    r.y = tanhf(s.y + v.y);
    r.z = tanhf(s.z + v.z);
    r.w = tanhf(s.w + v.w);
    ((float4*)out)[i] = r;
}

// ---------------------------------------------------------------------------
__global__ void __launch_bounds__(256) level_small(
    const float* __restrict__ childs,
    const float* __restrict__ Wl,
    const float* __restrict__ Wr,
    const float* __restrict__ vecs,
    float* __restrict__ out)
{
    __shared__ float G[512];
    __shared__ float partl[8][33];
    const int tid = threadIdx.x;
    const int p   = blockIdx.x >> 3;
    const int cg  = blockIdx.x & 7;
    const float c23 = 2.0f / 3.0f, c13 = 1.0f / 3.0f;

    {
        const float* cb = childs + (size_t)p * 1024;
        int j = tid;
        G[j] = cb[j] + c23 * cb[256 + j] + c13 * cb[512 + j];
        G[256 + j] = c13 * cb[256 + j] + c23 * cb[512 + j] + cb[768 + j];
    }
    __syncthreads();

    const int cc = tid & 31;
    const int kg = tid >> 5;
    const int n  = cg * 32 + cc;
    const float* src = (kg < 4) ? (Wl + (size_t)n * 256 + kg * 64)
                                : (Wr + (size_t)n * 256 + (kg - 4) * 64);
    const float* g = G + kg * 64;

    float a0 = 0.f, a1 = 0.f, a2 = 0.f, a3 = 0.f;
#pragma unroll
    for (int i = 0; i < 64; i += 4) {
        float4 w = *(const float4*)(src + i);
        float4 gg = *(const float4*)(g + i);
        a0 = fmaf(gg.x, w.x, a0);
        a1 = fmaf(gg.y, w.y, a1);
        a2 = fmaf(gg.z, w.z, a2);
        a3 = fmaf(gg.w, w.w, a3);
    }
    partl[kg][cc] = (a0 + a1) + (a2 + a3);
    __syncthreads();

    if (tid < 32) {
        float s = 0.f;
#pragma unroll
        for (int k = 0; k < 8; k++) s += partl[k][tid];
        const int col = cg * 32 + tid;
        out[(size_t)p * 256 + col] = tanhf(s + vecs[(size_t)p * 256 + col]);
    }
}

// ---------------------------------------------------------------------------
extern "C" void kernel_launch(void* const* d_in, const int* in_sizes, int n_in,
                              void* d_out, int out_size) {
    const float* vectors = (const float*)d_in[0];
    const float* Wl = (const float*)d_in[1];
    const float* Wr = (const float*)d_in[2];

    static float *h0, *h1, *part;
    static bool inited = false;
    if (!inited) {
        cudaGetSymbolAddress((void**)&h0, g_h0);
        cudaGetSymbolAddress((void**)&h1, g_h1);
        cudaGetSymbolAddress((void**)&part, g_part);
        cudaFuncSetAttribute(mma_l7,
                             cudaFuncAttributeMaxDynamicSharedMemorySize, W_SMEM);
        cudaFuncSetAttribute(mma_mid,
                             cudaFuncAttributeMaxDynamicSharedMemorySize, N_SMEM);
        inited = true;
    }

    const float* leaves = vectors + (size_t)21845 * 256;
    const float* v7 = vectors + (size_t)5461 * 256;
    const float* v6 = vectors + (size_t)1365 * 256;
    const float* v5 = vectors + (size_t)341 * 256;
    const float* v4 = vectors + (size_t)85 * 256;
    const float* v3 = vectors + (size_t)21 * 256;
    const float* v2 = vectors + (size_t)5 * 256;
    const float* v1 = vectors + (size_t)1 * 256;
    const float* v0 = vectors;

    prep_b<<<512, 256>>>(Wl, Wr);

    // l7: 16384 parents, wide fused kernel -> h7 (g_h0)
    mma_l7<<<256, 512, W_SMEM>>>(leaves, v7, h0);

    // l6: 4096 parents, narrow z=4 (nc=4) -> 16MB partials -> h6 (g_h1)
    {
        size_t zs = (size_t)4096 * 256;
        mma_mid<<<dim3(64, 2, 4), 256, N_SMEM>>>(h0, part, 4, zs);
        reduce_tanh<<<(unsigned)(zs / 1024), 256>>>(part, v6, h1, 4, zs);
    }
    // l5: 1024 parents, narrow z=8 (nc=2) -> 8MB partials -> h5 (g_h0)
    {
        size_t zs = (size_t)1024 * 256;
        mma_mid<<<dim3(16, 2, 8), 256, N_SMEM>>>(h1, part, 2, zs);
        reduce_tanh<<<(unsigned)(zs / 1024), 256>>>(part, v5, h0, 8, zs);
    }
    // l4..l0: fp32 SIMT chain
    level_small<<<256 * 8, 256>>>(h0, Wl, Wr, v4, h1);
    level_small<<<64 * 8, 256>>>(h1, Wl, Wr, v3, h0);
    level_small<<<16 * 8, 256>>>(h0, Wl, Wr, v2, h1);
    level_small<<<4 * 8, 256>>>(h1, Wl, Wr, v1, h0);
    level_small<<<1 * 8, 256>>>(h0, Wl, Wr, v0, (float*)d_out);
}